// round 4
// baseline (speedup 1.0000x reference)
#include <cuda_runtime.h>
#include <cstdint>

#define N_NODES 40000
#define D 128
#define N_EDGES 640000

// Scratch: allocation-free per harness rules.
__device__ float g_agg[(size_t)N_NODES * D];   // 20.5 MB
__device__ float g_deg[N_NODES];

// ---------------------------------------------------------------------------
// Kernel 1: zero the scratch accumulators.
// ---------------------------------------------------------------------------
__global__ void gcn_zero_kernel() {
    const int stride = gridDim.x * blockDim.x;
    int i = blockIdx.x * blockDim.x + threadIdx.x;
    float4 z = make_float4(0.f, 0.f, 0.f, 0.f);
    const int n_agg4 = N_NODES * D / 4;      // 1,280,000
    for (int idx = i; idx < n_agg4; idx += stride)
        reinterpret_cast<float4*>(g_agg)[idx] = z;
    const int n_deg4 = N_NODES / 4;          // 10,000
    for (int idx = i; idx < n_deg4; idx += stride)
        reinterpret_cast<float4*>(g_deg)[idx] = z;
}

// ---------------------------------------------------------------------------
// Kernel 2: edge scatter. One warp per edge; each lane handles 4 floats of
// the 128-float row via LDG.128 + red.global.add.v4.f32 (no-return vector
// reduction -> 1 REDG.128 per lane instead of 4 scalar atomics).
// Lane 0 also bumps the out-degree counter of src.
// NOTE: indices are int32 (JAX x64-disabled downcasts the reference's int64).
// ---------------------------------------------------------------------------
__global__ void gcn_scatter_kernel(const float* __restrict__ h,
                                   const int* __restrict__ src,
                                   const int* __restrict__ dst) {
    const int lane   = threadIdx.x & 31;
    const int gwarp  = (blockIdx.x * blockDim.x + threadIdx.x) >> 5;
    const int nwarps = (gridDim.x * blockDim.x) >> 5;

    for (int e = gwarp; e < N_EDGES; e += nwarps) {
        const int s = __ldg(&src[e]);
        const int d = __ldg(&dst[e]);

        const float4 v = *reinterpret_cast<const float4*>(h + (size_t)s * D + lane * 4);
        float* p = g_agg + (size_t)d * D + lane * 4;
        asm volatile("red.global.add.v4.f32 [%0], {%1, %2, %3, %4};"
                     :: "l"(p), "f"(v.x), "f"(v.y), "f"(v.z), "f"(v.w)
                     : "memory");

        if (lane == 0) {
            asm volatile("red.global.add.f32 [%0], %1;"
                         :: "l"(g_deg + s), "f"(1.0f)
                         : "memory");
        }
    }
}

// ---------------------------------------------------------------------------
// Kernel 3: out = relu(agg @ W * rsqrt(deg) + bias)
// 512 threads, tile M=128 rows x N=128 cols. W (64KB) + padded A tile (66KB)
// in dynamic smem. Each thread computes a 4x8 register tile (32 FFMA per k
// against 6 LDS -> ~84% FMA issue density).
// ---------------------------------------------------------------------------
#define MT 128
#define GEMM_THREADS 512
#define A_LD 129   // pad to avoid 16-way bank conflict on column reads

__global__ void gcn_gemm_kernel(const float* __restrict__ W,
                                const float* __restrict__ bias,
                                float* __restrict__ out) {
    extern __shared__ float smem[];
    float* Ws = smem;                 // [128][128]
    float* As = smem + D * D;         // [MT][A_LD]

    const int tid  = threadIdx.x;
    const int row0 = blockIdx.x * MT;

    // Cooperative load of W (16384 floats, float4-vectorized).
    for (int i = tid * 4; i < D * D; i += GEMM_THREADS * 4)
        *reinterpret_cast<float4*>(Ws + i) = *reinterpret_cast<const float4*>(W + i);

    // Cooperative load of the A tile (rows may run past N_NODES -> zeros).
    for (int idx = tid; idx < MT * (D / 4); idx += GEMM_THREADS) {
        const int r  = idx >> 5;         // / 32 float4 per row
        const int c4 = idx & 31;
        const int gr = row0 + r;
        float4 v = make_float4(0.f, 0.f, 0.f, 0.f);
        if (gr < N_NODES)
            v = *reinterpret_cast<const float4*>(g_agg + (size_t)gr * D + c4 * 4);
        float* p = As + r * A_LD + c4 * 4;
        p[0] = v.x; p[1] = v.y; p[2] = v.z; p[3] = v.w;
    }
    __syncthreads();

    const int tx = tid & 15;   // col group: cols [tx*8, tx*8+8)
    const int ty = tid >> 4;   // row group: rows [ty*4, ty*4+4)

    float acc[4][8];
#pragma unroll
    for (int i = 0; i < 4; i++)
#pragma unroll
        for (int j = 0; j < 8; j++) acc[i][j] = 0.f;

    const float* a_base = As + (ty * 4) * A_LD;
    const float* w_base = Ws + tx * 8;

#pragma unroll 4
    for (int k = 0; k < D; k++) {
        float a0 = a_base[0 * A_LD + k];
        float a1 = a_base[1 * A_LD + k];
        float a2 = a_base[2 * A_LD + k];
        float a3 = a_base[3 * A_LD + k];
        float4 w0 = *reinterpret_cast<const float4*>(w_base + k * D);
        float4 w1 = *reinterpret_cast<const float4*>(w_base + k * D + 4);
        const float wv[8] = {w0.x, w0.y, w0.z, w0.w, w1.x, w1.y, w1.z, w1.w};
#pragma unroll
        for (int j = 0; j < 8; j++) {
            acc[0][j] = fmaf(a0, wv[j], acc[0][j]);
            acc[1][j] = fmaf(a1, wv[j], acc[1][j]);
            acc[2][j] = fmaf(a2, wv[j], acc[2][j]);
            acc[3][j] = fmaf(a3, wv[j], acc[3][j]);
        }
    }

    // Epilogue: * rsqrt(deg) + bias, relu, store.
    const float4 b0 = *reinterpret_cast<const float4*>(bias + tx * 8);
    const float4 b1 = *reinterpret_cast<const float4*>(bias + tx * 8 + 4);
    const float bv[8] = {b0.x, b0.y, b0.z, b0.w, b1.x, b1.y, b1.z, b1.w};

#pragma unroll
    for (int i = 0; i < 4; i++) {
        const int r = row0 + ty * 4 + i;
        if (r >= N_NODES) continue;
        const float nrm = rsqrtf(g_deg[r]);
        float o[8];
#pragma unroll
        for (int j = 0; j < 8; j++) {
            float v = fmaf(acc[i][j], nrm, bv[j]);
            o[j] = v > 0.f ? v : 0.f;
        }
        float* op = out + (size_t)r * D + tx * 8;
        *reinterpret_cast<float4*>(op)     = make_float4(o[0], o[1], o[2], o[3]);
        *reinterpret_cast<float4*>(op + 4) = make_float4(o[4], o[5], o[6], o[7]);
    }
}

// ---------------------------------------------------------------------------
// Launch: inputs per metadata order: h[f32], src[i32], dst[i32], kernel[f32],
// bias[f32]. Output f32 [40000,128].
// ---------------------------------------------------------------------------
extern "C" void kernel_launch(void* const* d_in, const int* in_sizes, int n_in,
                              void* d_out, int out_size) {
    const float* h    = (const float*)d_in[0];
    const int*   src  = (const int*)d_in[1];
    const int*   dst  = (const int*)d_in[2];
    const float* W    = (const float*)d_in[3];
    const float* bias = (const float*)d_in[4];
    float* out = (float*)d_out;

    (void)in_sizes; (void)n_in; (void)out_size;

    // 1. zero accumulators
    gcn_zero_kernel<<<1184, 256>>>();

    // 2. edge scatter: 160000 warps, 4 edges per warp
    gcn_scatter_kernel<<<20000, 256>>>(h, src, dst);

    // 3. GEMM + fused epilogue (set smem attribute every call; host-side,
    //    not captured, deterministic).
    const int smem_bytes = (D * D + MT * A_LD) * (int)sizeof(float);  // 131,584 B
    cudaFuncSetAttribute(gcn_gemm_kernel,
                         cudaFuncAttributeMaxDynamicSharedMemorySize, smem_bytes);
    const int grid = (N_NODES + MT - 1) / MT;  // 313
    gcn_gemm_kernel<<<grid, GEMM_THREADS, smem_bytes>>>(W, bias, out);
}